// round 14
// baseline (speedup 1.0000x reference)
#include <cuda_runtime.h>
#include <math.h>
#include <float.h>
#include <stdint.h>

// Problem constants
#define NS 25      // support count
#define NQ 75      // query count
#define DD 640     // feature dim
#define MM 25      // inner dim (padded to 32 = 4 k-steps of 8)
#define NPB 125    // producer blocks: 25 s x 5 d-tiles of 128
#define NCB 375    // consumer blocks: 75 q x 5 d-tiles of 128

// Scratch (device globals; counters return to 0 within each launch)
__device__ float g_P[NQ * NS * DD];    // P[q][s][d]
__device__ float g_part[NQ * NS * 8];  // per-(q,s): 5 tile partials (pad 8)
__device__ int   g_prod[8];            // producer-done count per d-tile
__device__ int   g_cons[8];            // consumer-done count per d-tile
__device__ int   g_cnt[NQ];            // softmax tickets per q

// tf32 convert (round-to-nearest-with-ties-to-away per mma spec)
__device__ __forceinline__ uint32_t f2tf32(float x) {
    uint32_t r;
    asm("cvt.rna.tf32.f32 %0, %1;" : "=r"(r) : "f"(x));
    return r;
}

// m16n8k8 row.col f32 = tf32 x tf32 + f32  (fallback HMMA on sm_103)
__device__ __forceinline__ void mma_tf32(float* c, const uint32_t* a,
                                         const uint32_t* b) {
    asm volatile(
        "mma.sync.aligned.m16n8k8.row.col.f32.tf32.tf32.f32 "
        "{%0,%1,%2,%3}, {%4,%5,%6,%7}, {%8,%9}, {%0,%1,%2,%3};"
        : "+f"(c[0]), "+f"(c[1]), "+f"(c[2]), "+f"(c[3])
        : "r"(a[0]), "r"(a[1]), "r"(a[2]), "r"(a[3]),
          "r"(b[0]), "r"(b[1]));
}

// Shared pool layout (floats):
//  producer: Afrag @0 (4096), Bfrag @4096 (2560), out @6656 (2112)
//  consumer: Afrag @0 (4096), Bfrag @4096 (1024);
//            after MMA: rsm @0 (3300), psum @5120 (800)
#define POOL_FLOATS 8768
#define BOFF 4096
#define OOFF 6656
#define PSUM 5120

// Fragment address helpers (PTX m16n8k8 layouts).
// A (16x8, row-major): a0=(g,t) a1=(g+8,t) a2=(g,t+4) a3=(g+8,t+4)
__device__ __forceinline__ int a_slot(int d, int m) {
    int mt = d >> 4, r = d & 15, k = m >> 3, c = m & 7;
    int lane = ((r & 7) << 2) | (c & 3);
    int reg  = (r >> 3) | ((c >> 2) << 1);
    return ((mt * 4 + k) * 32 + lane) * 4 + reg;
}
// B (8x8, col-major): b0=(k=t, n=g) b1=(k=t+4, n=g)
__device__ __forceinline__ int b_slot(int n, int m) {
    int nt = n >> 3, k = m >> 3, kr = m & 7;
    int lane = ((n & 7) << 2) | (kr & 3);
    int reg  = kr >> 2;
    return ((nt * 4 + k) * 32 + lane) * 2 + reg;
}

__global__ __launch_bounds__(128, 4) void fused_mma(
        const float* __restrict__ fm, const float* __restrict__ w2,
        const float* __restrict__ scale, float* __restrict__ out) {
    __shared__ __align__(16) float pool[POOL_FLOATS];
    __shared__ int s_last;

    const int bid  = blockIdx.x;
    const int tid  = threadIdx.x;   // 128
    const int lane = tid & 31;
    const int w    = tid >> 5;      // warp 0..3; owns mtiles {w, w+4}
    const int g    = lane >> 2;     // fragment groupID
    const int t    = lane & 3;      // fragment threadID_in_group

    const bool is_prod = (bid < NPB);
    const int  dt = is_prod ? (bid % 5) : ((bid - NPB) % 5);
    const int  sq = is_prod ? (bid / 5) : ((bid - NPB) / 5);   // s or q

    // ---- Zero frag regions (covers k-pad m=25..31 and n-pad rows) --------
    for (int j = tid; j < 6656 / 4; j += 128)
        *reinterpret_cast<float4*>(&pool[j * 4]) = make_float4(0, 0, 0, 0);
    __syncthreads();

    // ---- Stage A fragments: 128 d-rows x 25 m (tf32) ----------------------
    {
        const float* src = is_prod
            ? &fm[sq * (DD * MM) + dt * 128 * MM]
            : &fm[(NS + sq) * (DD * MM) + dt * 128 * MM];
        int d = tid / 25, m = tid - (tid / 25) * 25;
        for (int idx = tid; idx < 128 * MM; idx += 128) {
            pool[a_slot(d, m)] = __uint_as_float(f2tf32(src[idx]));
            m += 3; d += 5;
            if (m >= 25) { m -= 25; d += 1; }
        }
    }
    // ---- Stage B fragments: producer 75 q-rows, consumer 25 s-rows --------
    if (is_prod) {
        const float* src = &w2[sq * (NQ * MM)];        // [q][m] linear
        int n = tid / 25, m = tid - (tid / 25) * 25;
        for (int idx = tid; idx < NQ * MM; idx += 128) {
            pool[BOFF + b_slot(n, m)] = __uint_as_float(f2tf32(src[idx]));
            m += 3; n += 5;
            if (m >= 25) { m -= 25; n += 1; }
        }
    } else {
        int n = tid / 25, m = tid - (tid / 25) * 25;
        for (int idx = tid; idx < NS * MM; idx += 128) {
            float v = w2[(n * NQ + sq) * MM + m];
            pool[BOFF + b_slot(n, m)] = __uint_as_float(f2tf32(v));
            m += 3; n += 5;
            if (m >= 25) { m -= 25; n += 1; }
        }
    }
    __syncthreads();

    if (is_prod) {
        // ============ Producer: D[128d x 80q] in 5 chunks of 16 q ==========
        const int s = sq;
        for (int c = 0; c < 5; c++) {
            float acc[2][2][4];
#pragma unroll
            for (int i = 0; i < 2; i++)
#pragma unroll
                for (int nn = 0; nn < 2; nn++)
#pragma unroll
                    for (int r = 0; r < 4; r++) acc[i][nn][r] = 0.0f;

#pragma unroll
            for (int k = 0; k < 4; k++) {
                uint4 a0 = *reinterpret_cast<const uint4*>(
                    &pool[(w * 4 + k) * 128 + lane * 4]);
                uint4 a1 = *reinterpret_cast<const uint4*>(
                    &pool[((w + 4) * 4 + k) * 128 + lane * 4]);
#pragma unroll
                for (int nn = 0; nn < 2; nn++) {
                    int nt = 2 * c + nn;
                    uint2 b = *reinterpret_cast<const uint2*>(
                        &pool[BOFF + ((nt * 4 + k) * 32 + lane) * 2]);
                    mma_tf32(acc[0][nn], reinterpret_cast<uint32_t*>(&a0),
                             reinterpret_cast<uint32_t*>(&b));
                    mma_tf32(acc[1][nn], reinterpret_cast<uint32_t*>(&a1),
                             reinterpret_cast<uint32_t*>(&b));
                }
            }

            __syncthreads();   // previous chunk's copy done; out reusable
            // D layout: c0=(g,2t) c1=(g,2t+1) c2=(g+8,2t) c3=(g+8,2t+1)
#pragma unroll
            for (int i = 0; i < 2; i++) {
                int dbase = (w + 4 * i) * 16 + g;
#pragma unroll
                for (int nn = 0; nn < 2; nn++)
#pragma unroll
                    for (int r = 0; r < 4; r++) {
                        int ql = nn * 8 + 2 * t + (r & 1);
                        if (c * 16 + ql < NQ)
                            pool[OOFF + ql * 132 + dbase + 8 * (r >> 1)] =
                                acc[i][nn][r];
                    }
            }
            __syncthreads();
            // Coalesced copy to g_P[q][s][d]
            for (int j = tid; j < 512; j += 128) {
                int ql = j >> 5, d4 = (j & 31) * 4;
                int q  = c * 16 + ql;
                if (q < NQ) {
                    float4 v = *reinterpret_cast<const float4*>(
                        &pool[OOFF + ql * 132 + d4]);
                    *reinterpret_cast<float4*>(
                        &g_P[(q * NS + s) * DD + dt * 128 + d4]) = v;
                }
            }
        }
        __threadfence();       // release P before flag
        __syncthreads();
        if (tid == 0) atomicAdd(&g_prod[dt], 1);
    } else {
        // ============ Consumer: r = D[128d x 32s], then (p-r)^2 ============
        const int q = sq;
        float acc[2][4][4];
#pragma unroll
        for (int i = 0; i < 2; i++)
#pragma unroll
            for (int n = 0; n < 4; n++)
#pragma unroll
                for (int r = 0; r < 4; r++) acc[i][n][r] = 0.0f;

#pragma unroll
        for (int k = 0; k < 4; k++) {
            uint4 a0 = *reinterpret_cast<const uint4*>(
                &pool[(w * 4 + k) * 128 + lane * 4]);
            uint4 a1 = *reinterpret_cast<const uint4*>(
                &pool[((w + 4) * 4 + k) * 128 + lane * 4]);
#pragma unroll
            for (int n = 0; n < 4; n++) {
                uint2 b = *reinterpret_cast<const uint2*>(
                    &pool[BOFF + ((n * 4 + k) * 32 + lane) * 2]);
                mma_tf32(acc[0][n], reinterpret_cast<uint32_t*>(&a0),
                         reinterpret_cast<uint32_t*>(&b));
                mma_tf32(acc[1][n], reinterpret_cast<uint32_t*>(&a1),
                         reinterpret_cast<uint32_t*>(&b));
            }
        }
        __syncthreads();       // frags dead; alias rsm over them

        // STS r into rsm[s][d] (stride 132: conflict-free per STS)
#pragma unroll
        for (int i = 0; i < 2; i++) {
            int dbase = (w + 4 * i) * 16 + g;
#pragma unroll
            for (int n = 0; n < 4; n++)
#pragma unroll
                for (int r = 0; r < 4; r++) {
                    int sv = n * 8 + 2 * t + (r & 1);
                    if (sv < NS)
                        pool[sv * 132 + dbase + 8 * (r >> 1)] = acc[i][n][r];
                }
        }

        // Wait for all 25 producers of this d-tile
        if (tid == 0) {
            while (*(volatile int*)&g_prod[dt] < NS) __nanosleep(64);
        }
        __syncthreads();
        __threadfence();       // acquire producer P stores

        // pass1: (p - r)^2, 4 d at a time, coalesced LDG
        for (int j = tid; j < 800; j += 128) {
            int sv = j >> 5, d4 = (j & 31) * 4;
            float4 r4 = *reinterpret_cast<const float4*>(&pool[sv * 132 + d4]);
            float4 p4 = __ldcg(reinterpret_cast<const float4*>(
                &g_P[(q * NS + sv) * DD + dt * 128 + d4]));
            float t0 = r4.x - p4.x, t1 = r4.y - p4.y;
            float t2 = r4.z - p4.z, t3 = r4.w - p4.w;
            pool[PSUM + j] = t0 * t0 + t1 * t1 + t2 * t2 + t3 * t3;
        }
        __syncthreads();
        // pass2: 25 threads sum 32 partials each
        if (tid < NS) {
            float sum = 0.0f;
#pragma unroll
            for (int b8 = 0; b8 < 8; b8++) {
                float4 v = *reinterpret_cast<const float4*>(
                    &pool[PSUM + tid * 32 + b8 * 4]);
                sum += v.x + v.y + v.z + v.w;
            }
            g_part[(q * NS + tid) * 8 + dt] = sum;
        }
        __threadfence();
        __syncthreads();

        // Ticket + flag reset (R12 tail)
        if (tid == 0) {
            int oc = atomicAdd(&g_cons[dt], 1);
            if (oc == NQ - 1) { g_prod[dt] = 0; g_cons[dt] = 0; }
            s_last = (atomicAdd(&g_cnt[q], 1) == 4) ? 1 : 0;
        }
        __syncthreads();

        if (s_last && tid < 32) {
            __threadfence();   // acquire all 5 partials for this q
            const float cc = -scale[0] / 312500.0f;  // 1/(M^2 * G*Q*Q*SHOT)
            float raw = 0.0f;
            if (lane < NS) {
                const float* p = &g_part[(q * NS + lane) * 8];
                float4 v4 = __ldcg(reinterpret_cast<const float4*>(p));
                raw = v4.x + v4.y + v4.z + v4.w + __ldcg(&p[4]);
            }
            float logit = (lane < NS) ? raw * cc : -FLT_MAX;

            float mx = logit;
#pragma unroll
            for (int off = 16; off > 0; off >>= 1)
                mx = fmaxf(mx, __shfl_xor_sync(0xffffffffu, mx, off));
            float e = (lane < NS) ? expf(logit - mx) : 0.0f;
            float sum = e;
#pragma unroll
            for (int off = 16; off > 0; off >>= 1)
                sum += __shfl_xor_sync(0xffffffffu, sum, off);

            if (lane < NS)
                out[q * NS + lane] = logit - mx - logf(sum);
            if (lane == 0) g_cnt[q] = 0;
        }
    }
}

// ---------------------------------------------------------------------------
extern "C" void kernel_launch(void* const* d_in, const int* in_sizes, int n_in,
                              void* d_out, int out_size) {
    const float* fm    = (const float*)d_in[0];  // (100, 640, 25) f32
    const float* w2    = (const float*)d_in[1];  // (25, 75, 25) f32
    const float* scale = (const float*)d_in[2];  // (1,) f32
    float* out = (float*)d_out;                  // (75, 25) f32

    fused_mma<<<NPB + NCB, 128>>>(fm, w2, scale, out);
}

// round 15
// speedup vs baseline: 1.1214x; 1.1214x over previous
#include <cuda_runtime.h>
#include <math.h>
#include <float.h>
#include <stdint.h>

// Problem constants
#define NS 25      // support count
#define NQ 75      // query count
#define DD 640     // feature dim
#define MM 25      // inner dim (padded to 32 = 4 k-steps of 8)
#define NPB 125    // producer blocks: 25 s x 5 d-tiles of 128
#define NCB 375    // consumer blocks: 75 q x 5 d-tiles of 128

// Scratch (device globals; counters return to 0 within each launch)
__device__ float g_P[NQ * NS * DD];    // P[q][s][d]
__device__ float g_part[NQ * NS * 8];  // per-(q,s): 5 tile partials (pad 8)
__device__ int   g_prod[8];            // producer-done count per d-tile
__device__ int   g_cons[8];            // consumer-done count per d-tile
__device__ int   g_cnt[NQ];            // softmax tickets per q

__device__ __forceinline__ uint32_t f2tf32(float x) {
    uint32_t r;
    asm("cvt.rna.tf32.f32 %0, %1;" : "=r"(r) : "f"(x));
    return r;
}
__device__ __forceinline__ uint32_t F2U(float x) { return __float_as_uint(x); }

// m16n8k8 row.col f32 = tf32 x tf32 + f32 (fallback HMMA on sm_103; verified R14)
__device__ __forceinline__ void mma_tf32(float* c, const uint32_t* a,
                                         const uint32_t* b) {
    asm volatile(
        "mma.sync.aligned.m16n8k8.row.col.f32.tf32.tf32.f32 "
        "{%0,%1,%2,%3}, {%4,%5,%6,%7}, {%8,%9}, {%0,%1,%2,%3};"
        : "+f"(c[0]), "+f"(c[1]), "+f"(c[2]), "+f"(c[3])
        : "r"(a[0]), "r"(a[1]), "r"(a[2]), "r"(a[3]),
          "r"(b[0]), "r"(b[1]));
}

// Pool (floats): A tile @0: 128x36 = 4608; B tile @4608: up to 80x36 = 2880.
// Consumer reuse after MMA: rsm[s][d] (stride 132) @0 (max 4220 < 4608);
// psum @4608 (800 floats).
#define POOL 7488
#define BOFF 4608
#define PSUM 4608

__global__ __launch_bounds__(256, 4) void fused_mma2(
        const float* __restrict__ fm, const float* __restrict__ w2,
        const float* __restrict__ scale, float* __restrict__ out) {
    __shared__ __align__(16) float pool[POOL];
    __shared__ int s_last;

    const int bid  = blockIdx.x;
    const int tid  = threadIdx.x;   // 256
    const int lane = tid & 31;
    const int w    = tid >> 5;      // warp 0..7, owns mtile w (16 d rows)
    const int g    = lane >> 2;     // fragment groupID (0..7)
    const int t    = lane & 3;      // fragment threadID_in_group (0..3)

    const bool is_prod = (bid < NPB);
    const int  dt = is_prod ? (bid % 5) : ((bid - NPB) % 5);
    const int  sq = is_prod ? (bid / 5) : ((bid - NPB) / 5);  // s or q

    // ---- Zero pool (k-pad m=25..31, B row pads) ---------------------------
    for (int j = tid; j < POOL / 4; j += 256)
        *reinterpret_cast<float4*>(&pool[j * 4]) = make_float4(0, 0, 0, 0);
    __syncthreads();

    // ---- Stage: threads 0..127 -> A rows; threads 128.. -> B rows ---------
    if (tid < 128) {
        const float* src = is_prod
            ? &fm[sq * (DD * MM) + dt * 128 * MM + tid * MM]
            : &fm[(NS + sq) * (DD * MM) + dt * 128 * MM + tid * MM];
        float v[25];
#pragma unroll
        for (int m = 0; m < 25; m++)
            v[m] = __uint_as_float(f2tf32(src[m]));
#pragma unroll
        for (int i = 0; i < 6; i++)
            *reinterpret_cast<float4*>(&pool[tid * 36 + i * 4]) =
                make_float4(v[i*4], v[i*4+1], v[i*4+2], v[i*4+3]);
        pool[tid * 36 + 24] = v[24];
    } else {
        const int row   = tid - 128;
        const int nrows = is_prod ? NQ : NS;
        if (row < nrows) {
            const float* src = is_prod
                ? &w2[sq * (NQ * MM) + row * MM]       // W[s][q=row][m]
                : &w2[(row * NQ + sq) * MM];           // W[s=row][q][m]
            float v[25];
#pragma unroll
            for (int m = 0; m < 25; m++)
                v[m] = __uint_as_float(f2tf32(src[m]));
#pragma unroll
            for (int i = 0; i < 6; i++)
                *reinterpret_cast<float4*>(&pool[BOFF + row * 36 + i * 4]) =
                    make_float4(v[i*4], v[i*4+1], v[i*4+2], v[i*4+3]);
            pool[BOFF + row * 36 + 24] = v[24];
        }
    }
    __syncthreads();

    const int arow0 = (w * 16 + g) * 36 + t;   // A frag base (this warp)

    if (is_prod) {
        // ========= Producer: D[128d x 80q] = A . B^T in 2 passes of 5 nt ===
        const int s = sq;
#pragma unroll
        for (int p = 0; p < 2; p++) {
            float acc[5][4];
#pragma unroll
            for (int nt = 0; nt < 5; nt++)
#pragma unroll
                for (int r = 0; r < 4; r++) acc[nt][r] = 0.0f;

#pragma unroll
            for (int k = 0; k < 4; k++) {
                uint32_t a[4];
                a[0] = F2U(pool[arow0 + k * 8]);
                a[1] = F2U(pool[arow0 + 288 + k * 8]);        // +8 rows
                a[2] = F2U(pool[arow0 + k * 8 + 4]);
                a[3] = F2U(pool[arow0 + 288 + k * 8 + 4]);
#pragma unroll
                for (int nt = 0; nt < 5; nt++) {
                    int nrow = ((p * 5 + nt) * 8 + g) * 36;
                    uint32_t b[2];
                    b[0] = F2U(pool[BOFF + nrow + k * 8 + t]);
                    b[1] = F2U(pool[BOFF + nrow + k * 8 + t + 4]);
                    mma_tf32(acc[nt], a, b);
                }
            }
            // D frag: c0=(g,2t) c1=(g,2t+1) c2=(g+8,2t) c3=(g+8,2t+1)
#pragma unroll
            for (int nt = 0; nt < 5; nt++)
#pragma unroll
                for (int r = 0; r < 4; r++) {
                    int q = (p * 5 + nt) * 8 + 2 * t + (r & 1);
                    int d = dt * 128 + w * 16 + g + 8 * (r >> 1);
                    if (q < NQ)
                        g_P[(q * NS + s) * DD + d] = acc[nt][r];
                }
        }
        __threadfence();       // release P before flag
        __syncthreads();
        if (tid == 0) atomicAdd(&g_prod[dt], 1);
    } else {
        // ========= Consumer: r = D[128d x 32s]; then (p-r)^2 ===============
        const int q = sq;
        float acc[4][4];
#pragma unroll
        for (int nt = 0; nt < 4; nt++)
#pragma unroll
            for (int r = 0; r < 4; r++) acc[nt][r] = 0.0f;

#pragma unroll
        for (int k = 0; k < 4; k++) {
            uint32_t a[4];
            a[0] = F2U(pool[arow0 + k * 8]);
            a[1] = F2U(pool[arow0 + 288 + k * 8]);
            a[2] = F2U(pool[arow0 + k * 8 + 4]);
            a[3] = F2U(pool[arow0 + 288 + k * 8 + 4]);
#pragma unroll
            for (int nt = 0; nt < 4; nt++) {
                int nrow = (nt * 8 + g) * 36;
                uint32_t b[2];
                b[0] = F2U(pool[BOFF + nrow + k * 8 + t]);
                b[1] = F2U(pool[BOFF + nrow + k * 8 + t + 4]);
                mma_tf32(acc[nt], a, b);
            }
        }
        __syncthreads();       // all warps done reading A/B; reuse pool as rsm

        // STS r fragments -> rsm[s][d-local], stride 132 (conflict-free)
#pragma unroll
        for (int nt = 0; nt < 4; nt++)
#pragma unroll
            for (int r = 0; r < 4; r++) {
                int sv = nt * 8 + 2 * t + (r & 1);     // <=31; pad rows ok
                int dl = w * 16 + g + 8 * (r >> 1);
                pool[sv * 132 + dl] = acc[nt][r];
            }

        // Wait for all 25 producers of this d-tile
        if (tid == 0) {
            while (*(volatile int*)&g_prod[dt] < NS) __nanosleep(64);
        }
        __syncthreads();       // rsm visible + spin released
        __threadfence();       // acquire producer P stores

        // pass1: (p - r)^2 over 4-d groups, coalesced LDG of P
        for (int j = tid; j < 800; j += 256) {
            int sv = j >> 5, d4 = (j & 31) * 4;
            float4 r4 = *reinterpret_cast<const float4*>(&pool[sv * 132 + d4]);
            float4 p4 = __ldcg(reinterpret_cast<const float4*>(
                &g_P[(q * NS + sv) * DD + dt * 128 + d4]));
            float t0 = r4.x - p4.x, t1 = r4.y - p4.y;
            float t2 = r4.z - p4.z, t3 = r4.w - p4.w;
            pool[PSUM + j] = t0 * t0 + t1 * t1 + t2 * t2 + t3 * t3;
        }
        __syncthreads();
        // pass2: 25 threads sum their 32 partials
        if (tid < NS) {
            float sum = 0.0f;
#pragma unroll
            for (int b8 = 0; b8 < 8; b8++) {
                float4 v = *reinterpret_cast<const float4*>(
                    &pool[PSUM + tid * 32 + b8 * 4]);
                sum += v.x + v.y + v.z + v.w;
            }
            g_part[(q * NS + tid) * 8 + dt] = sum;
        }
        __threadfence();
        __syncthreads();

        // Ticket + flag reset (verified R12 tail)
        if (tid == 0) {
            int oc = atomicAdd(&g_cons[dt], 1);
            if (oc == NQ - 1) { g_prod[dt] = 0; g_cons[dt] = 0; }
            s_last = (atomicAdd(&g_cnt[q], 1) == 4) ? 1 : 0;
        }
        __syncthreads();

        if (s_last && tid < 32) {
            __threadfence();   // acquire all 5 partials for this q
            const float cc = -scale[0] / 312500.0f;  // 1/(M^2 * G*Q*Q*SHOT)
            float raw = 0.0f;
            if (lane < NS) {
                const float* p = &g_part[(q * NS + lane) * 8];
                float4 v4 = __ldcg(reinterpret_cast<const float4*>(p));
                raw = v4.x + v4.y + v4.z + v4.w + __ldcg(&p[4]);
            }
            float logit = (lane < NS) ? raw * cc : -FLT_MAX;

            float mx = logit;
#pragma unroll
            for (int off = 16; off > 0; off >>= 1)
                mx = fmaxf(mx, __shfl_xor_sync(0xffffffffu, mx, off));
            float e = (lane < NS) ? expf(logit - mx) : 0.0f;
            float sum = e;
#pragma unroll
            for (int off = 16; off > 0; off >>= 1)
                sum += __shfl_xor_sync(0xffffffffu, sum, off);

            if (lane < NS)
                out[q * NS + lane] = logit - mx - logf(sum);
            if (lane == 0) g_cnt[q] = 0;
        }
    }
}

// ---------------------------------------------------------------------------
extern "C" void kernel_launch(void* const* d_in, const int* in_sizes, int n_in,
                              void* d_out, int out_size) {
    const float* fm    = (const float*)d_in[0];  // (100, 640, 25) f32
    const float* w2    = (const float*)d_in[1];  // (25, 75, 25) f32
    const float* scale = (const float*)d_in[2];  // (1,) f32
    float* out = (float*)d_out;                  // (75, 25) f32

    fused_mma2<<<NPB + NCB, 256>>>(fm, w2, scale, out);
}